// round 14
// baseline (speedup 1.0000x reference)
#include <cuda_runtime.h>
#include <cuda_fp16.h>

#define NN 100000
#define NE 3200000
#define NEG 0.2f

// ---- read-only node payloads (never RED targets) ----
__device__ __align__(16) uint4  g_h1p[NN];      // h1 as 8 x fp16
__device__ float  g_ad1[NN];                    // dst logit, layer 1 (fp32)
__device__ unsigned g_o2h[NN];                  // (o0, o1) as half2
__device__ float  g_ad2n[NN];                   // dst logit, layer 2 (fp32)

// ---- RED-only accumulators (never read during edge kernels) ----
struct __align__(32) A1 {                       // both REDs share one 32B sector
    uint4 hacc;      // 8 x fp16 accumulator
    float den;       // fp32 denominator
    float pad[3];
};
__device__ A1 g_acc1[NN];
__device__ __align__(16) float4 g_acc2[NN];     // (accx, accy, den, -)

// ---- layer-1 node kernel: h1 = x@W1 (fp32), pack fp16; init acc ----
// 256 nodes/block; x staged via float4 (36 = 4*9 -> no row crossing)
__global__ __launch_bounds__(256) void k_node1(
    const float4* __restrict__ x4, const float* __restrict__ W1,
    const float* __restrict__ ad1)
{
    __shared__ float xs[256 * 37];   // pad 36->37: conflict-free reads
    __shared__ float Ws[36 * 8];
    __shared__ float dv[8];
    const int t = threadIdx.x;
    const int base = blockIdx.x * 256;

    for (int i = t; i < 36 * 8; i += 256) Ws[i] = W1[i];
    if (t < 8) dv[t] = ad1[t];

    int nrows = NN - base; if (nrows > 256) nrows = 256;
    const int nvec = nrows * 9;                 // float4s this block
    for (int k = t; k < nvec; k += 256) {
        const float4 v = x4[base * 9 + k];      // coalesced LDG.128
        const int g = k * 4;
        const int r = g / 36, c = g % 36;       // never crosses a row
        float* p = &xs[r * 37 + c];
        p[0] = v.x; p[1] = v.y; p[2] = v.z; p[3] = v.w;
    }
    __syncthreads();

    const int node = base + t;
    if (node >= NN) return;

    float h[8];
#pragma unroll
    for (int k = 0; k < 8; k++) h[k] = 0.f;
#pragma unroll
    for (int j = 0; j < 36; j++) {
        const float xv = xs[t * 37 + j];
#pragma unroll
        for (int k = 0; k < 8; k++) h[k] = fmaf(xv, Ws[j * 8 + k], h[k]);
    }

    float d = 0.f;
#pragma unroll
    for (int k = 0; k < 8; k++) d = fmaf(h[k], dv[k], d);

    __half2 p0 = __floats2half2_rn(h[0], h[1]);
    __half2 p1 = __floats2half2_rn(h[2], h[3]);
    __half2 p2 = __floats2half2_rn(h[4], h[5]);
    __half2 p3 = __floats2half2_rn(h[6], h[7]);
    uint4 hp;
    hp.x = *reinterpret_cast<unsigned*>(&p0);
    hp.y = *reinterpret_cast<unsigned*>(&p1);
    hp.z = *reinterpret_cast<unsigned*>(&p2);
    hp.w = *reinterpret_cast<unsigned*>(&p3);
    g_h1p[node] = hp;
    g_ad1[node] = d;

    A1 z;
    z.hacc = make_uint4(0u, 0u, 0u, 0u);
    z.den = 0.f; z.pad[0] = z.pad[1] = z.pad[2] = 0.f;
    g_acc1[node] = z;
    g_acc2[node] = make_float4(0.f, 0.f, 0.f, 0.f);
}

// ---- layer-1 edge kernel: 8 edges/thread; 4 wavefronts per edge ----
__global__ __launch_bounds__(256) void k_edge1(
    const int4* __restrict__ eis, const int4* __restrict__ eid,
    const float* __restrict__ as1)
{
    const int t = blockIdx.x * 256 + threadIdx.x;
    if (t >= NE / 8) return;

    const float av0 = __ldg(&as1[0]), av1 = __ldg(&as1[1]);
    const float av2 = __ldg(&as1[2]), av3 = __ldg(&as1[3]);
    const float av4 = __ldg(&as1[4]), av5 = __ldg(&as1[5]);
    const float av6 = __ldg(&as1[6]), av7 = __ldg(&as1[7]);

    const int4 sa = eis[t * 2], sb = eis[t * 2 + 1];
    const int4 da = eid[t * 2], db = eid[t * 2 + 1];
    const int ss[8] = { sa.x, sa.y, sa.z, sa.w, sb.x, sb.y, sb.z, sb.w };
    const int dd[8] = { da.x, da.y, da.z, da.w, db.x, db.y, db.z, db.w };

#pragma unroll
    for (int q = 0; q < 8; q++) {
        const int s = ss[q];
        const int d = dd[q];
        if ((unsigned)s >= NN || (unsigned)d >= NN) continue;

        const uint4 hp = g_h1p[s];        // gather 1 (16B)
        const float ad = g_ad1[d];        // gather 2 (4B)

        const float2 f0 = __half22float2(*reinterpret_cast<const __half2*>(&hp.x));
        const float2 f1 = __half22float2(*reinterpret_cast<const __half2*>(&hp.y));
        const float2 f2 = __half22float2(*reinterpret_cast<const __half2*>(&hp.z));
        const float2 f3 = __half22float2(*reinterpret_cast<const __half2*>(&hp.w));

        float as = f0.x * av0;
        as = fmaf(f0.y, av1, as);
        as = fmaf(f1.x, av2, as);
        as = fmaf(f1.y, av3, as);
        as = fmaf(f2.x, av4, as);
        as = fmaf(f2.y, av5, as);
        as = fmaf(f3.x, av6, as);
        as = fmaf(f3.y, av7, as);

        float ev = as + ad;
        ev = ev > 0.f ? ev : NEG * ev;
        const float w = __expf(ev);

        __half2 w0 = __floats2half2_rn(w * f0.x, w * f0.y);
        __half2 w1 = __floats2half2_rn(w * f1.x, w * f1.y);
        __half2 w2 = __floats2half2_rn(w * f2.x, w * f2.y);
        __half2 w3 = __floats2half2_rn(w * f3.x, w * f3.y);
        asm volatile("red.global.add.noftz.v4.f16x2 [%0], {%1,%2,%3,%4};" ::
            "l"(&g_acc1[d].hacc),
            "r"(*reinterpret_cast<unsigned*>(&w0)),
            "r"(*reinterpret_cast<unsigned*>(&w1)),
            "r"(*reinterpret_cast<unsigned*>(&w2)),
            "r"(*reinterpret_cast<unsigned*>(&w3)) : "memory");
        atomicAdd(&g_acc1[d].den, w);
    }
}

// ---- layer-2 node kernel: relu(agg1+b1) @ W2; pack o as half2 ----
__global__ __launch_bounds__(256) void k_node2(
    const float* __restrict__ b1, const float* __restrict__ W2,
    const float* __restrict__ ad2)
{
    const int i = blockIdx.x * 256 + threadIdx.x;
    if (i >= NN) return;

    const uint4 ap = g_acc1[i].hacc;
    const float den = g_acc1[i].den;
    const float2 a0 = __half22float2(*reinterpret_cast<const __half2*>(&ap.x));
    const float2 a1 = __half22float2(*reinterpret_cast<const __half2*>(&ap.y));
    const float2 a2 = __half22float2(*reinterpret_cast<const __half2*>(&ap.z));
    const float2 a3 = __half22float2(*reinterpret_cast<const __half2*>(&ap.w));
    const float inv = den > 0.f ? 1.0f / den : 0.f;

    float h[8];
    h[0] = fmaxf(fmaf(a0.x, inv, __ldg(&b1[0])), 0.f);
    h[1] = fmaxf(fmaf(a0.y, inv, __ldg(&b1[1])), 0.f);
    h[2] = fmaxf(fmaf(a1.x, inv, __ldg(&b1[2])), 0.f);
    h[3] = fmaxf(fmaf(a1.y, inv, __ldg(&b1[3])), 0.f);
    h[4] = fmaxf(fmaf(a2.x, inv, __ldg(&b1[4])), 0.f);
    h[5] = fmaxf(fmaf(a2.y, inv, __ldg(&b1[5])), 0.f);
    h[6] = fmaxf(fmaf(a3.x, inv, __ldg(&b1[6])), 0.f);
    h[7] = fmaxf(fmaf(a3.y, inv, __ldg(&b1[7])), 0.f);

    float o0 = 0.f, o1 = 0.f;
#pragma unroll
    for (int k = 0; k < 8; k++) {
        o0 = fmaf(h[k], __ldg(&W2[k * 2 + 0]), o0);
        o1 = fmaf(h[k], __ldg(&W2[k * 2 + 1]), o1);
    }
    __half2 op = __floats2half2_rn(o0, o1);
    g_o2h[i]  = *reinterpret_cast<unsigned*>(&op);
    g_ad2n[i] = fmaf(o0, __ldg(&ad2[0]), o1 * __ldg(&ad2[1]));
}

// ---- layer-2 edge kernel: 8 edges/thread; 3 wavefronts per edge ----
__global__ __launch_bounds__(256) void k_edge2(
    const int4* __restrict__ eis, const int4* __restrict__ eid,
    const float* __restrict__ as2)
{
    const int t = blockIdx.x * 256 + threadIdx.x;
    if (t >= NE / 8) return;

    const float a0 = __ldg(&as2[0]), a1 = __ldg(&as2[1]);

    const int4 sa = eis[t * 2], sb = eis[t * 2 + 1];
    const int4 da = eid[t * 2], db = eid[t * 2 + 1];
    const int ss[8] = { sa.x, sa.y, sa.z, sa.w, sb.x, sb.y, sb.z, sb.w };
    const int dd[8] = { da.x, da.y, da.z, da.w, db.x, db.y, db.z, db.w };

#pragma unroll
    for (int q = 0; q < 8; q++) {
        const int s = ss[q];
        const int d = dd[q];
        if ((unsigned)s >= NN || (unsigned)d >= NN) continue;

        const unsigned ou = g_o2h[s];     // gather 1 (4B, half2)
        const float ad = g_ad2n[d];       // gather 2 (4B)

        const float2 o = __half22float2(*reinterpret_cast<const __half2*>(&ou));
        float ev = fmaf(o.x, a0, o.y * a1) + ad;
        ev = ev > 0.f ? ev : NEG * ev;
        const float w = __expf(ev);

        atomicAdd(&g_acc2[d], make_float4(w * o.x, w * o.y, w, 0.f));
    }
}

// ---- final node kernel: normalize, +b2, log_softmax(2) ----
__global__ __launch_bounds__(256) void k_node3(
    const float* __restrict__ b2, float* __restrict__ out)
{
    const int i = blockIdx.x * 256 + threadIdx.x;
    if (i >= NN) return;

    const float4 a = g_acc2[i];
    const float inv = a.z > 0.f ? 1.0f / a.z : 0.f;
    const float o0 = fmaf(a.x, inv, __ldg(&b2[0]));
    const float o1 = fmaf(a.y, inv, __ldg(&b2[1]));
    const float m = fmaxf(o0, o1);
    const float lse = m + logf(expf(o0 - m) + expf(o1 - m));
    ((float2*)out)[i] = make_float2(o0 - lse, o1 - lse);
}

extern "C" void kernel_launch(void* const* d_in, const int* in_sizes, int n_in,
                              void* d_out, int out_size)
{
    int ix = -1, ie = -1, iw1 = -1, iw2 = -1;
    int i8[3] = {-1, -1, -1}, n8 = 0;
    int i2[3] = {-1, -1, -1}, n2 = 0;
    for (int i = 0; i < n_in; i++) {
        switch (in_sizes[i]) {
            case 3600000: ix = i; break;
            case 6400000: ie = i; break;
            case 288:     iw1 = i; break;
            case 16:      iw2 = i; break;
            case 8:  if (n8 < 3) i8[n8++] = i; break;
            case 2:  if (n2 < 3) i2[n2++] = i; break;
            default: break;
        }
    }
    int ias1, iad1, ib1, ias2, iad2, ib2;
    if (ix == 0) { ias1 = i8[0]; iad1 = i8[1]; ib1 = i8[2];
                   ias2 = i2[0]; iad2 = i2[1]; ib2 = i2[2]; }
    else         { iad1 = i8[0]; ias1 = i8[1]; ib1 = i8[2];
                   iad2 = i2[0]; ias2 = i2[1]; ib2 = i2[2]; }

    const float* x   = (const float*)d_in[ix];
    const int*   ei  = (const int*)d_in[ie];
    const float* W1  = (const float*)d_in[iw1];
    const float* as1 = (const float*)d_in[ias1];
    const float* ad1 = (const float*)d_in[iad1];
    const float* b1  = (const float*)d_in[ib1];
    const float* W2  = (const float*)d_in[iw2];
    const float* as2 = (const float*)d_in[ias2];
    const float* ad2 = (const float*)d_in[iad2];
    const float* b2  = (const float*)d_in[ib2];
    float* out = (float*)d_out;

    const int4* eis = (const int4*)ei;           // src row, quads
    const int4* eid = (const int4*)(ei + NE);    // dst row, quads

    const int nb_node1 = (NN + 255) / 256;
    const int nb_node  = (NN + 255) / 256;
    const int nb_edge8 = (NE / 8 + 255) / 256;   // 8 edges per thread

    k_node1<<<nb_node1, 256>>>((const float4*)x, W1, ad1);
    k_edge1<<<nb_edge8, 256>>>(eis, eid, as1);
    k_node2<<<nb_node, 256>>>(b1, W2, ad2);
    k_edge2<<<nb_edge8, 256>>>(eis, eid, as2);
    k_node3<<<nb_node, 256>>>(b2, out);
}

// round 15
// speedup vs baseline: 1.0672x; 1.0672x over previous
#include <cuda_runtime.h>
#include <cuda_fp16.h>

#define NN 100000
#define NE 3200000
#define NEG 0.2f

// ---- read-only node payloads (never RED targets) ----
__device__ __align__(16) uint4  g_h1p[NN];      // h1 as 8 x fp16
__device__ float  g_ad1[NN];                    // dst logit, layer 1 (fp32)
__device__ unsigned g_o2h[NN];                  // (o0, o1) as half2
__device__ float  g_ad2n[NN];                   // dst logit, layer 2 (fp32)

// ---- RED-only accumulators (never read during edge kernels) ----
struct __align__(32) A1 {                       // both REDs share one 32B sector
    uint4 hacc;      // 8 x fp16 accumulator
    float den;       // fp32 denominator
    float pad[3];
};
__device__ A1 g_acc1[NN];
__device__ __align__(16) float4 g_acc2[NN];     // (accx, accy, den, -)

// ---- layer-1 node kernel: h1 = x@W1 (fp32), pack fp16; init acc ----
// 256 nodes/block; x staged via float4 (36 = 4*9 -> no row crossing)
__global__ __launch_bounds__(256) void k_node1(
    const float4* __restrict__ x4, const float* __restrict__ W1,
    const float* __restrict__ ad1)
{
    __shared__ float xs[256 * 37];   // pad 36->37: conflict-free reads
    __shared__ float Ws[36 * 8];
    __shared__ float dv[8];
    const int t = threadIdx.x;
    const int base = blockIdx.x * 256;

    for (int i = t; i < 36 * 8; i += 256) Ws[i] = W1[i];
    if (t < 8) dv[t] = ad1[t];

    int nrows = NN - base; if (nrows > 256) nrows = 256;
    const int nvec = nrows * 9;                 // float4s this block
    for (int k = t; k < nvec; k += 256) {
        const float4 v = x4[base * 9 + k];      // coalesced LDG.128
        const int g = k * 4;
        const int r = g / 36, c = g % 36;       // never crosses a row
        float* p = &xs[r * 37 + c];
        p[0] = v.x; p[1] = v.y; p[2] = v.z; p[3] = v.w;
    }
    __syncthreads();

    const int node = base + t;
    if (node >= NN) return;

    float h[8];
#pragma unroll
    for (int k = 0; k < 8; k++) h[k] = 0.f;
#pragma unroll
    for (int j = 0; j < 36; j++) {
        const float xv = xs[t * 37 + j];
#pragma unroll
        for (int k = 0; k < 8; k++) h[k] = fmaf(xv, Ws[j * 8 + k], h[k]);
    }

    float d = 0.f;
#pragma unroll
    for (int k = 0; k < 8; k++) d = fmaf(h[k], dv[k], d);

    __half2 p0 = __floats2half2_rn(h[0], h[1]);
    __half2 p1 = __floats2half2_rn(h[2], h[3]);
    __half2 p2 = __floats2half2_rn(h[4], h[5]);
    __half2 p3 = __floats2half2_rn(h[6], h[7]);
    uint4 hp;
    hp.x = *reinterpret_cast<unsigned*>(&p0);
    hp.y = *reinterpret_cast<unsigned*>(&p1);
    hp.z = *reinterpret_cast<unsigned*>(&p2);
    hp.w = *reinterpret_cast<unsigned*>(&p3);
    g_h1p[node] = hp;
    g_ad1[node] = d;

    A1 z;
    z.hacc = make_uint4(0u, 0u, 0u, 0u);
    z.den = 0.f; z.pad[0] = z.pad[1] = z.pad[2] = 0.f;
    g_acc1[node] = z;
    g_acc2[node] = make_float4(0.f, 0.f, 0.f, 0.f);
}

// ---- layer-1 edge kernel: 4 edges/thread; 4 wavefronts per edge ----
__global__ __launch_bounds__(256) void k_edge1(
    const int4* __restrict__ eis, const int4* __restrict__ eid,
    const float* __restrict__ as1)
{
    const int t = blockIdx.x * 256 + threadIdx.x;
    if (t >= NE / 4) return;

    const float av0 = __ldg(&as1[0]), av1 = __ldg(&as1[1]);
    const float av2 = __ldg(&as1[2]), av3 = __ldg(&as1[3]);
    const float av4 = __ldg(&as1[4]), av5 = __ldg(&as1[5]);
    const float av6 = __ldg(&as1[6]), av7 = __ldg(&as1[7]);

    const int4 s4 = eis[t];
    const int4 d4 = eid[t];
    const int ss[4] = { s4.x, s4.y, s4.z, s4.w };
    const int dd[4] = { d4.x, d4.y, d4.z, d4.w };

#pragma unroll
    for (int q = 0; q < 4; q++) {
        const int s = ss[q];
        const int d = dd[q];
        if ((unsigned)s >= NN || (unsigned)d >= NN) continue;

        const uint4 hp = g_h1p[s];        // gather 1 (16B)
        const float ad = g_ad1[d];        // gather 2 (4B)

        const float2 f0 = __half22float2(*reinterpret_cast<const __half2*>(&hp.x));
        const float2 f1 = __half22float2(*reinterpret_cast<const __half2*>(&hp.y));
        const float2 f2 = __half22float2(*reinterpret_cast<const __half2*>(&hp.z));
        const float2 f3 = __half22float2(*reinterpret_cast<const __half2*>(&hp.w));

        float as = f0.x * av0;
        as = fmaf(f0.y, av1, as);
        as = fmaf(f1.x, av2, as);
        as = fmaf(f1.y, av3, as);
        as = fmaf(f2.x, av4, as);
        as = fmaf(f2.y, av5, as);
        as = fmaf(f3.x, av6, as);
        as = fmaf(f3.y, av7, as);

        float ev = as + ad;
        ev = ev > 0.f ? ev : NEG * ev;
        const float w = __expf(ev);

        __half2 w0 = __floats2half2_rn(w * f0.x, w * f0.y);
        __half2 w1 = __floats2half2_rn(w * f1.x, w * f1.y);
        __half2 w2 = __floats2half2_rn(w * f2.x, w * f2.y);
        __half2 w3 = __floats2half2_rn(w * f3.x, w * f3.y);
        // both REDs target the same 32B sector of g_acc1[d]
        asm volatile("red.global.add.noftz.v4.f16x2 [%0], {%1,%2,%3,%4};" ::
            "l"(&g_acc1[d].hacc),
            "r"(*reinterpret_cast<unsigned*>(&w0)),
            "r"(*reinterpret_cast<unsigned*>(&w1)),
            "r"(*reinterpret_cast<unsigned*>(&w2)),
            "r"(*reinterpret_cast<unsigned*>(&w3)) : "memory");
        atomicAdd(&g_acc1[d].den, w);
    }
}

// ---- layer-2 node kernel: relu(agg1+b1) @ W2; pack o as half2 ----
__global__ __launch_bounds__(256) void k_node2(
    const float* __restrict__ b1, const float* __restrict__ W2,
    const float* __restrict__ ad2)
{
    const int i = blockIdx.x * 256 + threadIdx.x;
    if (i >= NN) return;

    const uint4 ap = g_acc1[i].hacc;
    const float den = g_acc1[i].den;
    const float2 a0 = __half22float2(*reinterpret_cast<const __half2*>(&ap.x));
    const float2 a1 = __half22float2(*reinterpret_cast<const __half2*>(&ap.y));
    const float2 a2 = __half22float2(*reinterpret_cast<const __half2*>(&ap.z));
    const float2 a3 = __half22float2(*reinterpret_cast<const __half2*>(&ap.w));
    const float inv = den > 0.f ? 1.0f / den : 0.f;

    float h[8];
    h[0] = fmaxf(fmaf(a0.x, inv, __ldg(&b1[0])), 0.f);
    h[1] = fmaxf(fmaf(a0.y, inv, __ldg(&b1[1])), 0.f);
    h[2] = fmaxf(fmaf(a1.x, inv, __ldg(&b1[2])), 0.f);
    h[3] = fmaxf(fmaf(a1.y, inv, __ldg(&b1[3])), 0.f);
    h[4] = fmaxf(fmaf(a2.x, inv, __ldg(&b1[4])), 0.f);
    h[5] = fmaxf(fmaf(a2.y, inv, __ldg(&b1[5])), 0.f);
    h[6] = fmaxf(fmaf(a3.x, inv, __ldg(&b1[6])), 0.f);
    h[7] = fmaxf(fmaf(a3.y, inv, __ldg(&b1[7])), 0.f);

    float o0 = 0.f, o1 = 0.f;
#pragma unroll
    for (int k = 0; k < 8; k++) {
        o0 = fmaf(h[k], __ldg(&W2[k * 2 + 0]), o0);
        o1 = fmaf(h[k], __ldg(&W2[k * 2 + 1]), o1);
    }
    __half2 op = __floats2half2_rn(o0, o1);
    g_o2h[i]  = *reinterpret_cast<unsigned*>(&op);
    g_ad2n[i] = fmaf(o0, __ldg(&ad2[0]), o1 * __ldg(&ad2[1]));
}

// ---- layer-2 edge kernel: 4 edges/thread; 3 wavefronts per edge ----
__global__ __launch_bounds__(256) void k_edge2(
    const int4* __restrict__ eis, const int4* __restrict__ eid,
    const float* __restrict__ as2)
{
    const int t = blockIdx.x * 256 + threadIdx.x;
    if (t >= NE / 4) return;

    const float a0 = __ldg(&as2[0]), a1 = __ldg(&as2[1]);

    const int4 s4 = eis[t];
    const int4 d4 = eid[t];
    const int ss[4] = { s4.x, s4.y, s4.z, s4.w };
    const int dd[4] = { d4.x, d4.y, d4.z, d4.w };

#pragma unroll
    for (int q = 0; q < 4; q++) {
        const int s = ss[q];
        const int d = dd[q];
        if ((unsigned)s >= NN || (unsigned)d >= NN) continue;

        const unsigned ou = g_o2h[s];     // gather 1 (4B, half2)
        const float ad = g_ad2n[d];       // gather 2 (4B)

        const float2 o = __half22float2(*reinterpret_cast<const __half2*>(&ou));
        float ev = fmaf(o.x, a0, o.y * a1) + ad;
        ev = ev > 0.f ? ev : NEG * ev;
        const float w = __expf(ev);

        atomicAdd(&g_acc2[d], make_float4(w * o.x, w * o.y, w, 0.f));
    }
}

// ---- final node kernel: normalize, +b2, log_softmax(2) ----
__global__ __launch_bounds__(256) void k_node3(
    const float* __restrict__ b2, float* __restrict__ out)
{
    const int i = blockIdx.x * 256 + threadIdx.x;
    if (i >= NN) return;

    const float4 a = g_acc2[i];
    const float inv = a.z > 0.f ? 1.0f / a.z : 0.f;
    const float o0 = fmaf(a.x, inv, __ldg(&b2[0]));
    const float o1 = fmaf(a.y, inv, __ldg(&b2[1]));
    const float m = fmaxf(o0, o1);
    const float lse = m + logf(expf(o0 - m) + expf(o1 - m));
    ((float2*)out)[i] = make_float2(o0 - lse, o1 - lse);
}

extern "C" void kernel_launch(void* const* d_in, const int* in_sizes, int n_in,
                              void* d_out, int out_size)
{
    int ix = -1, ie = -1, iw1 = -1, iw2 = -1;
    int i8[3] = {-1, -1, -1}, n8 = 0;
    int i2[3] = {-1, -1, -1}, n2 = 0;
    for (int i = 0; i < n_in; i++) {
        switch (in_sizes[i]) {
            case 3600000: ix = i; break;
            case 6400000: ie = i; break;
            case 288:     iw1 = i; break;
            case 16:      iw2 = i; break;
            case 8:  if (n8 < 3) i8[n8++] = i; break;
            case 2:  if (n2 < 3) i2[n2++] = i; break;
            default: break;
        }
    }
    int ias1, iad1, ib1, ias2, iad2, ib2;
    if (ix == 0) { ias1 = i8[0]; iad1 = i8[1]; ib1 = i8[2];
                   ias2 = i2[0]; iad2 = i2[1]; ib2 = i2[2]; }
    else         { iad1 = i8[0]; ias1 = i8[1]; ib1 = i8[2];
                   iad2 = i2[0]; ias2 = i2[1]; ib2 = i2[2]; }

    const float* x   = (const float*)d_in[ix];
    const int*   ei  = (const int*)d_in[ie];
    const float* W1  = (const float*)d_in[iw1];
    const float* as1 = (const float*)d_in[ias1];
    const float* ad1 = (const float*)d_in[iad1];
    const float* b1  = (const float*)d_in[ib1];
    const float* W2  = (const float*)d_in[iw2];
    const float* as2 = (const float*)d_in[ias2];
    const float* ad2 = (const float*)d_in[iad2];
    const float* b2  = (const float*)d_in[ib2];
    float* out = (float*)d_out;

    const int4* eis = (const int4*)ei;           // src row, quads
    const int4* eid = (const int4*)(ei + NE);    // dst row, quads

    const int nb_node  = (NN + 255) / 256;
    const int nb_edge4 = (NE / 4 + 255) / 256;   // 4 edges per thread

    k_node1<<<nb_node, 256>>>((const float4*)x, W1, ad1);
    k_edge1<<<nb_edge4, 256>>>(eis, eid, as1);
    k_node2<<<nb_node, 256>>>(b1, W2, ad2);
    k_edge2<<<nb_edge4, 256>>>(eis, eid, as2);
    k_node3<<<nb_node, 256>>>(b2, out);
}

// round 16
// speedup vs baseline: 1.0703x; 1.0030x over previous
#include <cuda_runtime.h>
#include <cuda_fp16.h>

#define NN 100000
#define NE 3200000
#define NEG 0.2f

// ---- read-only node payloads (never RED targets) ----
__device__ __align__(16) uint4  g_h1p[NN];      // h1 as 8 x fp16
__device__ float  g_ad1[NN];                    // dst logit, layer 1 (fp32)
__device__ unsigned g_o2h[NN];                  // (o0, o1) as half2
__device__ float  g_ad2n[NN];                   // dst logit, layer 2 (fp32)

// ---- RED-only accumulators (never read during edge kernels) ----
struct __align__(32) A1 {                       // both REDs share one 32B sector
    uint4 hacc;      // 8 x fp16 accumulator
    float den;       // fp32 denominator
    float pad[3];
};
__device__ A1 g_acc1[NN];
__device__ __align__(16) float4 g_acc2[NN];     // (accx, accy, den, -)

// ---- layer-1 node kernel: h1 = x@W1, pack fp16; init acc1 ----
// direct 9 x LDG.128 per node (36 = 4*9, rows float4-aligned); no x staging
__global__ __launch_bounds__(256) void k_node1(
    const float4* __restrict__ x4, const float* __restrict__ W1,
    const float* __restrict__ ad1)
{
    __shared__ float Ws[36 * 8];
    __shared__ float dv[8];
    const int t = threadIdx.x;
    for (int i = t; i < 36 * 8; i += 256) Ws[i] = W1[i];
    if (t < 8) dv[t] = ad1[t];
    __syncthreads();

    const int node = blockIdx.x * 256 + t;
    if (node >= NN) return;

    float h[8];
#pragma unroll
    for (int k = 0; k < 8; k++) h[k] = 0.f;

    const float4* row = x4 + node * 9;
#pragma unroll
    for (int v = 0; v < 9; v++) {
        const float4 xv = row[v];               // LDG.128
        const float* wj = &Ws[v * 4 * 8];       // warp-uniform -> LDS broadcast
#pragma unroll
        for (int k = 0; k < 8; k++) h[k] = fmaf(xv.x, wj[k],      h[k]);
#pragma unroll
        for (int k = 0; k < 8; k++) h[k] = fmaf(xv.y, wj[8 + k],  h[k]);
#pragma unroll
        for (int k = 0; k < 8; k++) h[k] = fmaf(xv.z, wj[16 + k], h[k]);
#pragma unroll
        for (int k = 0; k < 8; k++) h[k] = fmaf(xv.w, wj[24 + k], h[k]);
    }

    float d = 0.f;
#pragma unroll
    for (int k = 0; k < 8; k++) d = fmaf(h[k], dv[k], d);

    __half2 p0 = __floats2half2_rn(h[0], h[1]);
    __half2 p1 = __floats2half2_rn(h[2], h[3]);
    __half2 p2 = __floats2half2_rn(h[4], h[5]);
    __half2 p3 = __floats2half2_rn(h[6], h[7]);
    uint4 hp;
    hp.x = *reinterpret_cast<unsigned*>(&p0);
    hp.y = *reinterpret_cast<unsigned*>(&p1);
    hp.z = *reinterpret_cast<unsigned*>(&p2);
    hp.w = *reinterpret_cast<unsigned*>(&p3);
    g_h1p[node] = hp;
    g_ad1[node] = d;

    A1 z;
    z.hacc = make_uint4(0u, 0u, 0u, 0u);
    z.den = 0.f; z.pad[0] = z.pad[1] = z.pad[2] = 0.f;
    g_acc1[node] = z;
}

// ---- layer-1 edge kernel: 4 edges/thread; 4 lane-requests per edge ----
__global__ __launch_bounds__(256) void k_edge1(
    const int4* __restrict__ eis, const int4* __restrict__ eid,
    const float* __restrict__ as1)
{
    const int t = blockIdx.x * 256 + threadIdx.x;
    if (t >= NE / 4) return;

    const float av0 = __ldg(&as1[0]), av1 = __ldg(&as1[1]);
    const float av2 = __ldg(&as1[2]), av3 = __ldg(&as1[3]);
    const float av4 = __ldg(&as1[4]), av5 = __ldg(&as1[5]);
    const float av6 = __ldg(&as1[6]), av7 = __ldg(&as1[7]);

    const int4 s4 = eis[t];
    const int4 d4 = eid[t];
    const int ss[4] = { s4.x, s4.y, s4.z, s4.w };
    const int dd[4] = { d4.x, d4.y, d4.z, d4.w };

#pragma unroll
    for (int q = 0; q < 4; q++) {
        const int s = ss[q];
        const int d = dd[q];
        if ((unsigned)s >= NN || (unsigned)d >= NN) continue;

        const uint4 hp = g_h1p[s];        // gather 1 (16B)
        const float ad = g_ad1[d];        // gather 2 (4B)

        const float2 f0 = __half22float2(*reinterpret_cast<const __half2*>(&hp.x));
        const float2 f1 = __half22float2(*reinterpret_cast<const __half2*>(&hp.y));
        const float2 f2 = __half22float2(*reinterpret_cast<const __half2*>(&hp.z));
        const float2 f3 = __half22float2(*reinterpret_cast<const __half2*>(&hp.w));

        float as = f0.x * av0;
        as = fmaf(f0.y, av1, as);
        as = fmaf(f1.x, av2, as);
        as = fmaf(f1.y, av3, as);
        as = fmaf(f2.x, av4, as);
        as = fmaf(f2.y, av5, as);
        as = fmaf(f3.x, av6, as);
        as = fmaf(f3.y, av7, as);

        float ev = as + ad;
        ev = ev > 0.f ? ev : NEG * ev;
        const float w = __expf(ev);

        __half2 w0 = __floats2half2_rn(w * f0.x, w * f0.y);
        __half2 w1 = __floats2half2_rn(w * f1.x, w * f1.y);
        __half2 w2 = __floats2half2_rn(w * f2.x, w * f2.y);
        __half2 w3 = __floats2half2_rn(w * f3.x, w * f3.y);
        // both REDs target the same 32B sector of g_acc1[d]
        asm volatile("red.global.add.noftz.v4.f16x2 [%0], {%1,%2,%3,%4};" ::
            "l"(&g_acc1[d].hacc),
            "r"(*reinterpret_cast<unsigned*>(&w0)),
            "r"(*reinterpret_cast<unsigned*>(&w1)),
            "r"(*reinterpret_cast<unsigned*>(&w2)),
            "r"(*reinterpret_cast<unsigned*>(&w3)) : "memory");
        atomicAdd(&g_acc1[d].den, w);
    }
}

// ---- layer-2 node kernel: relu(agg1+b1) @ W2; pack o; init acc2 ----
__global__ __launch_bounds__(256) void k_node2(
    const float* __restrict__ b1, const float* __restrict__ W2,
    const float* __restrict__ ad2)
{
    const int i = blockIdx.x * 256 + threadIdx.x;
    if (i >= NN) return;

    const uint4 ap = g_acc1[i].hacc;
    const float den = g_acc1[i].den;
    const float2 a0 = __half22float2(*reinterpret_cast<const __half2*>(&ap.x));
    const float2 a1 = __half22float2(*reinterpret_cast<const __half2*>(&ap.y));
    const float2 a2 = __half22float2(*reinterpret_cast<const __half2*>(&ap.z));
    const float2 a3 = __half22float2(*reinterpret_cast<const __half2*>(&ap.w));
    const float inv = den > 0.f ? 1.0f / den : 0.f;

    float h[8];
    h[0] = fmaxf(fmaf(a0.x, inv, __ldg(&b1[0])), 0.f);
    h[1] = fmaxf(fmaf(a0.y, inv, __ldg(&b1[1])), 0.f);
    h[2] = fmaxf(fmaf(a1.x, inv, __ldg(&b1[2])), 0.f);
    h[3] = fmaxf(fmaf(a1.y, inv, __ldg(&b1[3])), 0.f);
    h[4] = fmaxf(fmaf(a2.x, inv, __ldg(&b1[4])), 0.f);
    h[5] = fmaxf(fmaf(a2.y, inv, __ldg(&b1[5])), 0.f);
    h[6] = fmaxf(fmaf(a3.x, inv, __ldg(&b1[6])), 0.f);
    h[7] = fmaxf(fmaf(a3.y, inv, __ldg(&b1[7])), 0.f);

    float o0 = 0.f, o1 = 0.f;
#pragma unroll
    for (int k = 0; k < 8; k++) {
        o0 = fmaf(h[k], __ldg(&W2[k * 2 + 0]), o0);
        o1 = fmaf(h[k], __ldg(&W2[k * 2 + 1]), o1);
    }
    __half2 op = __floats2half2_rn(o0, o1);
    g_o2h[i]  = *reinterpret_cast<unsigned*>(&op);
    g_ad2n[i] = fmaf(o0, __ldg(&ad2[0]), o1 * __ldg(&ad2[1]));
    g_acc2[i] = make_float4(0.f, 0.f, 0.f, 0.f);
}

// ---- layer-2 edge kernel: 4 edges/thread; 3 lane-requests per edge ----
__global__ __launch_bounds__(256) void k_edge2(
    const int4* __restrict__ eis, const int4* __restrict__ eid,
    const float* __restrict__ as2)
{
    const int t = blockIdx.x * 256 + threadIdx.x;
    if (t >= NE / 4) return;

    const float a0 = __ldg(&as2[0]), a1 = __ldg(&as2[1]);

    const int4 s4 = eis[t];
    const int4 d4 = eid[t];
    const int ss[4] = { s4.x, s4.y, s4.z, s4.w };
    const int dd[4] = { d4.x, d4.y, d4.z, d4.w };

#pragma unroll
    for (int q = 0; q < 4; q++) {
        const int s = ss[q];
        const int d = dd[q];
        if ((unsigned)s >= NN || (unsigned)d >= NN) continue;

        const unsigned ou = g_o2h[s];     // gather 1 (4B, half2)
        const float ad = g_ad2n[d];       // gather 2 (4B)

        const float2 o = __half22float2(*reinterpret_cast<const __half2*>(&ou));
        float ev = fmaf(o.x, a0, o.y * a1) + ad;
        ev = ev > 0.f ? ev : NEG * ev;
        const float w = __expf(ev);

        atomicAdd(&g_acc2[d], make_float4(w * o.x, w * o.y, w, 0.f));
    }
}

// ---- final node kernel: normalize, +b2, log_softmax(2) ----
__global__ __launch_bounds__(256) void k_node3(
    const float* __restrict__ b2, float* __restrict__ out)
{
    const int i = blockIdx.x * 256 + threadIdx.x;
    if (i >= NN) return;

    const float4 a = g_acc2[i];
    const float inv = a.z > 0.f ? 1.0f / a.z : 0.f;
    const float o0 = fmaf(a.x, inv, __ldg(&b2[0]));
    const float o1 = fmaf(a.y, inv, __ldg(&b2[1]));
    const float m = fmaxf(o0, o1);
    const float lse = m + logf(expf(o0 - m) + expf(o1 - m));
    ((float2*)out)[i] = make_float2(o0 - lse, o1 - lse);
}

extern "C" void kernel_launch(void* const* d_in, const int* in_sizes, int n_in,
                              void* d_out, int out_size)
{
    int ix = -1, ie = -1, iw1 = -1, iw2 = -1;
    int i8[3] = {-1, -1, -1}, n8 = 0;
    int i2[3] = {-1, -1, -1}, n2 = 0;
    for (int i = 0; i < n_in; i++) {
        switch (in_sizes[i]) {
            case 3600000: ix = i; break;
            case 6400000: ie = i; break;
            case 288:     iw1 = i; break;
            case 16:      iw2 = i; break;
            case 8:  if (n8 < 3) i8[n8++] = i; break;
            case 2:  if (n2 < 3) i2[n2++] = i; break;
            default: break;
        }
    }
    int ias1, iad1, ib1, ias2, iad2, ib2;
    if (ix == 0) { ias1 = i8[0]; iad1 = i8[1]; ib1 = i8[2];
                   ias2 = i2[0]; iad2 = i2[1]; ib2 = i2[2]; }
    else         { iad1 = i8[0]; ias1 = i8[1]; ib1 = i8[2];
                   iad2 = i2[0]; ias2 = i2[1]; ib2 = i2[2]; }

    const float* x   = (const float*)d_in[ix];
    const int*   ei  = (const int*)d_in[ie];
    const float* W1  = (const float*)d_in[iw1];
    const float* as1 = (const float*)d_in[ias1];
    const float* ad1 = (const float*)d_in[iad1];
    const float* b1  = (const float*)d_in[ib1];
    const float* W2  = (const float*)d_in[iw2];
    const float* as2 = (const float*)d_in[ias2];
    const float* ad2 = (const float*)d_in[iad2];
    const float* b2  = (const float*)d_in[ib2];
    float* out = (float*)d_out;

    const int4* eis = (const int4*)ei;           // src row, quads
    const int4* eid = (const int4*)(ei + NE);    // dst row, quads

    const int nb_node  = (NN + 255) / 256;
    const int nb_edge4 = (NE / 4 + 255) / 256;   // 4 edges per thread

    k_node1<<<nb_node, 256>>>((const float4*)x, W1, ad1);
    k_edge1<<<nb_edge4, 256>>>(eis, eid, as1);
    k_node2<<<nb_node, 256>>>(b1, W2, ad2);
    k_edge2<<<nb_edge4, 256>>>(eis, eid, as2);
    k_node3<<<nb_node, 256>>>(b2, out);
}

// round 17
// speedup vs baseline: 1.0710x; 1.0007x over previous
#include <cuda_runtime.h>
#include <cuda_fp16.h>

#define NN 100000
#define NE 3200000
#define NEG 0.2f

// ---- read-only node payloads (never RED targets) ----
__device__ __align__(16) uint4  g_h1p[NN];      // h1 as 8 x fp16
__device__ float  g_ad1[NN];                    // dst logit, layer 1 (fp32)
__device__ unsigned g_o2h[NN];                  // (o0, o1) as half2
__device__ float  g_ad2n[NN];                   // dst logit, layer 2 (fp32)

// ---- RED-only accumulators (never read during edge kernels) ----
struct __align__(32) A1 {                       // both REDs share one 32B sector
    uint4 hacc;      // 8 x fp16 accumulator
    float den;       // fp32 denominator
    float pad[3];
};
__device__ A1 g_acc1[NN];
__device__ __align__(16) float4 g_acc2[NN];     // (accx, accy, den, -)

// ---- layer-1 node kernel: h1 = x@W1, pack fp16; init acc1 ----
// direct 9 x LDG.128 per node (36 = 4*9, rows float4-aligned); no x staging
__global__ __launch_bounds__(256) void k_node1(
    const float4* __restrict__ x4, const float* __restrict__ W1,
    const float* __restrict__ ad1)
{
    __shared__ float Ws[36 * 8];
    __shared__ float dv[8];
    const int t = threadIdx.x;
    for (int i = t; i < 36 * 8; i += 256) Ws[i] = W1[i];
    if (t < 8) dv[t] = ad1[t];
    __syncthreads();

    const int node = blockIdx.x * 256 + t;
    if (node >= NN) return;

    float h[8];
#pragma unroll
    for (int k = 0; k < 8; k++) h[k] = 0.f;

    const float4* row = x4 + node * 9;
#pragma unroll
    for (int v = 0; v < 9; v++) {
        const float4 xv = row[v];               // LDG.128
        const float* wj = &Ws[v * 4 * 8];       // warp-uniform -> LDS broadcast
#pragma unroll
        for (int k = 0; k < 8; k++) h[k] = fmaf(xv.x, wj[k],      h[k]);
#pragma unroll
        for (int k = 0; k < 8; k++) h[k] = fmaf(xv.y, wj[8 + k],  h[k]);
#pragma unroll
        for (int k = 0; k < 8; k++) h[k] = fmaf(xv.z, wj[16 + k], h[k]);
#pragma unroll
        for (int k = 0; k < 8; k++) h[k] = fmaf(xv.w, wj[24 + k], h[k]);
    }

    float d = 0.f;
#pragma unroll
    for (int k = 0; k < 8; k++) d = fmaf(h[k], dv[k], d);

    __half2 p0 = __floats2half2_rn(h[0], h[1]);
    __half2 p1 = __floats2half2_rn(h[2], h[3]);
    __half2 p2 = __floats2half2_rn(h[4], h[5]);
    __half2 p3 = __floats2half2_rn(h[6], h[7]);
    uint4 hp;
    hp.x = *reinterpret_cast<unsigned*>(&p0);
    hp.y = *reinterpret_cast<unsigned*>(&p1);
    hp.z = *reinterpret_cast<unsigned*>(&p2);
    hp.w = *reinterpret_cast<unsigned*>(&p3);
    g_h1p[node] = hp;
    g_ad1[node] = d;

    A1 z;
    z.hacc = make_uint4(0u, 0u, 0u, 0u);
    z.den = 0.f; z.pad[0] = z.pad[1] = z.pad[2] = 0.f;
    g_acc1[node] = z;
}

// ---- layer-1 edge kernel: 4 edges/thread; 4 lane-requests per edge ----
__global__ __launch_bounds__(256) void k_edge1(
    const int4* __restrict__ eis, const int4* __restrict__ eid,
    const float* __restrict__ as1)
{
    const int t = blockIdx.x * 256 + threadIdx.x;
    if (t >= NE / 4) return;

    const float av0 = __ldg(&as1[0]), av1 = __ldg(&as1[1]);
    const float av2 = __ldg(&as1[2]), av3 = __ldg(&as1[3]);
    const float av4 = __ldg(&as1[4]), av5 = __ldg(&as1[5]);
    const float av6 = __ldg(&as1[6]), av7 = __ldg(&as1[7]);

    const int4 s4 = eis[t];
    const int4 d4 = eid[t];
    const int ss[4] = { s4.x, s4.y, s4.z, s4.w };
    const int dd[4] = { d4.x, d4.y, d4.z, d4.w };

#pragma unroll
    for (int q = 0; q < 4; q++) {
        const int s = ss[q];
        const int d = dd[q];

        const uint4 hp = g_h1p[s];        // gather 1 (16B)
        const float ad = g_ad1[d];        // gather 2 (4B)

        const float2 f0 = __half22float2(*reinterpret_cast<const __half2*>(&hp.x));
        const float2 f1 = __half22float2(*reinterpret_cast<const __half2*>(&hp.y));
        const float2 f2 = __half22float2(*reinterpret_cast<const __half2*>(&hp.z));
        const float2 f3 = __half22float2(*reinterpret_cast<const __half2*>(&hp.w));

        float as = f0.x * av0;
        as = fmaf(f0.y, av1, as);
        as = fmaf(f1.x, av2, as);
        as = fmaf(f1.y, av3, as);
        as = fmaf(f2.x, av4, as);
        as = fmaf(f2.y, av5, as);
        as = fmaf(f3.x, av6, as);
        as = fmaf(f3.y, av7, as);

        const float z = as + ad;
        const float ev = fmaxf(z, NEG * z);   // branchless leaky_relu
        const float w = __expf(ev);

        __half2 w0 = __floats2half2_rn(w * f0.x, w * f0.y);
        __half2 w1 = __floats2half2_rn(w * f1.x, w * f1.y);
        __half2 w2 = __floats2half2_rn(w * f2.x, w * f2.y);
        __half2 w3 = __floats2half2_rn(w * f3.x, w * f3.y);
        // both REDs target the same 32B sector of g_acc1[d]
        asm volatile("red.global.add.noftz.v4.f16x2 [%0], {%1,%2,%3,%4};" ::
            "l"(&g_acc1[d].hacc),
            "r"(*reinterpret_cast<unsigned*>(&w0)),
            "r"(*reinterpret_cast<unsigned*>(&w1)),
            "r"(*reinterpret_cast<unsigned*>(&w2)),
            "r"(*reinterpret_cast<unsigned*>(&w3)) : "memory");
        atomicAdd(&g_acc1[d].den, w);
    }
}

// ---- layer-2 node kernel: relu(agg1+b1) @ W2; pack o; init acc2 ----
__global__ __launch_bounds__(256) void k_node2(
    const float* __restrict__ b1, const float* __restrict__ W2,
    const float* __restrict__ ad2)
{
    const int i = blockIdx.x * 256 + threadIdx.x;
    if (i >= NN) return;

    const uint4 ap = g_acc1[i].hacc;
    const float den = g_acc1[i].den;
    const float2 a0 = __half22float2(*reinterpret_cast<const __half2*>(&ap.x));
    const float2 a1 = __half22float2(*reinterpret_cast<const __half2*>(&ap.y));
    const float2 a2 = __half22float2(*reinterpret_cast<const __half2*>(&ap.z));
    const float2 a3 = __half22float2(*reinterpret_cast<const __half2*>(&ap.w));
    const float inv = den > 0.f ? 1.0f / den : 0.f;

    float h[8];
    h[0] = fmaxf(fmaf(a0.x, inv, __ldg(&b1[0])), 0.f);
    h[1] = fmaxf(fmaf(a0.y, inv, __ldg(&b1[1])), 0.f);
    h[2] = fmaxf(fmaf(a1.x, inv, __ldg(&b1[2])), 0.f);
    h[3] = fmaxf(fmaf(a1.y, inv, __ldg(&b1[3])), 0.f);
    h[4] = fmaxf(fmaf(a2.x, inv, __ldg(&b1[4])), 0.f);
    h[5] = fmaxf(fmaf(a2.y, inv, __ldg(&b1[5])), 0.f);
    h[6] = fmaxf(fmaf(a3.x, inv, __ldg(&b1[6])), 0.f);
    h[7] = fmaxf(fmaf(a3.y, inv, __ldg(&b1[7])), 0.f);

    float o0 = 0.f, o1 = 0.f;
#pragma unroll
    for (int k = 0; k < 8; k++) {
        o0 = fmaf(h[k], __ldg(&W2[k * 2 + 0]), o0);
        o1 = fmaf(h[k], __ldg(&W2[k * 2 + 1]), o1);
    }
    __half2 op = __floats2half2_rn(o0, o1);
    g_o2h[i]  = *reinterpret_cast<unsigned*>(&op);
    g_ad2n[i] = fmaf(o0, __ldg(&ad2[0]), o1 * __ldg(&ad2[1]));
    g_acc2[i] = make_float4(0.f, 0.f, 0.f, 0.f);
}

// ---- layer-2 edge kernel: 4 edges/thread; 3 lane-requests per edge ----
__global__ __launch_bounds__(256) void k_edge2(
    const int4* __restrict__ eis, const int4* __restrict__ eid,
    const float* __restrict__ as2)
{
    const int t = blockIdx.x * 256 + threadIdx.x;
    if (t >= NE / 4) return;

    const float a0 = __ldg(&as2[0]), a1 = __ldg(&as2[1]);

    const int4 s4 = eis[t];
    const int4 d4 = eid[t];
    const int ss[4] = { s4.x, s4.y, s4.z, s4.w };
    const int dd[4] = { d4.x, d4.y, d4.z, d4.w };

#pragma unroll
    for (int q = 0; q < 4; q++) {
        const int s = ss[q];
        const int d = dd[q];

        const unsigned ou = g_o2h[s];     // gather 1 (4B, half2)
        const float ad = g_ad2n[d];       // gather 2 (4B)

        const float2 o = __half22float2(*reinterpret_cast<const __half2*>(&ou));
        const float z = fmaf(o.x, a0, o.y * a1) + ad;
        const float ev = fmaxf(z, NEG * z);   // branchless leaky_relu
        const float w = __expf(ev);

        atomicAdd(&g_acc2[d], make_float4(w * o.x, w * o.y, w, 0.f));
    }
}

// ---- final node kernel: normalize, +b2, log_softmax(2) ----
__global__ __launch_bounds__(256) void k_node3(
    const float* __restrict__ b2, float* __restrict__ out)
{
    const int i = blockIdx.x * 256 + threadIdx.x;
    if (i >= NN) return;

    const float4 a = g_acc2[i];
    const float inv = a.z > 0.f ? 1.0f / a.z : 0.f;
    const float o0 = fmaf(a.x, inv, __ldg(&b2[0]));
    const float o1 = fmaf(a.y, inv, __ldg(&b2[1]));
    const float m = fmaxf(o0, o1);
    const float lse = m + logf(expf(o0 - m) + expf(o1 - m));
    ((float2*)out)[i] = make_float2(o0 - lse, o1 - lse);
}

extern "C" void kernel_launch(void* const* d_in, const int* in_sizes, int n_in,
                              void* d_out, int out_size)
{
    int ix = -1, ie = -1, iw1 = -1, iw2 = -1;
    int i8[3] = {-1, -1, -1}, n8 = 0;
    int i2[3] = {-1, -1, -1}, n2 = 0;
    for (int i = 0; i < n_in; i++) {
        switch (in_sizes[i]) {
            case 3600000: ix = i; break;
            case 6400000: ie = i; break;
            case 288:     iw1 = i; break;
            case 16:      iw2 = i; break;
            case 8:  if (n8 < 3) i8[n8++] = i; break;
            case 2:  if (n2 < 3) i2[n2++] = i; break;
            default: break;
        }
    }
    int ias1, iad1, ib1, ias2, iad2, ib2;
    if (ix == 0) { ias1 = i8[0]; iad1 = i8[1]; ib1 = i8[2];
                   ias2 = i2[0]; iad2 = i2[1]; ib2 = i2[2]; }
    else         { iad1 = i8[0]; ias1 = i8[1]; ib1 = i8[2];
                   iad2 = i2[0]; ias2 = i2[1]; ib2 = i2[2]; }

    const float* x   = (const float*)d_in[ix];
    const int*   ei  = (const int*)d_in[ie];
    const float* W1  = (const float*)d_in[iw1];
    const float* as1 = (const float*)d_in[ias1];
    const float* ad1 = (const float*)d_in[iad1];
    const float* b1  = (const float*)d_in[ib1];
    const float* W2  = (const float*)d_in[iw2];
    const float* as2 = (const float*)d_in[ias2];
    const float* ad2 = (const float*)d_in[iad2];
    const float* b2  = (const float*)d_in[ib2];
    float* out = (float*)d_out;

    const int4* eis = (const int4*)ei;           // src row, quads
    const int4* eid = (const int4*)(ei + NE);    // dst row, quads

    const int nb_node  = (NN + 255) / 256;
    const int nb_edge4 = (NE / 4 + 255) / 256;   // 4 edges per thread

    k_node1<<<nb_node, 256>>>((const float4*)x, W1, ad1);
    k_edge1<<<nb_edge4, 256>>>(eis, eid, as1);
    k_node2<<<nb_node, 256>>>(b1, W2, ad2);
    k_edge2<<<nb_edge4, 256>>>(eis, eid, as2);
    k_node3<<<nb_node, 256>>>(b2, out);
}